// round 15
// baseline (speedup 1.0000x reference)
#include <cuda_runtime.h>
#include <cstdint>

#define B_   16
#define N_   2048
#define F_   128
#define HID_ 32
#define FC_  512
#define C_   10

// ---- xw kernel (tf32 mma.sync, 512 threads) ----
#define XBM  128
#define BK   32
#define XMB  (N_ / XBM)    // 16
#define XS_  3
#define XNKT (F_ / BK)     // 4
#define ASTR 36
#define BSTR 40
#define XAPITCH (XBM * ASTR)
#define BPITCH  (BK * BSTR)
#define XW_SMEM ((XS_ * XAPITCH + XS_ * BPITCH) * 4)     // ~70 KB

// ---- main kernel (tf32 mma.sync, BM=256, 512 threads, 5-stage) ----
#define BM2  256
#define MB2  (N_ / BM2)    // 8
#define NKT  (N_ / BK)     // 64
#define S2   5
#define A2PITCH (BM2 * ASTR)
#define MAIN_SMEM ((S2 * A2PITCH + S2 * BPITCH) * 4)     // ~210 KB

// Scratch (no cudaMalloc allowed)
__device__ float g_XW[B_ * N_ * HID_];         // X @ W1  [B,N,32] fp32
__device__ float g_part[B_ * MB2 * HID_];      // per-block relu column sums

// ---------------- helpers ----------------
__device__ __forceinline__ void cp16(float* dst, const float* src) {
    unsigned s = (unsigned)__cvta_generic_to_shared(dst);
    asm volatile("cp.async.cg.shared.global [%0], [%1], 16;" :: "r"(s), "l"(src));
}
__device__ __forceinline__ void cp_commit() { asm volatile("cp.async.commit_group;"); }
template <int NN>
__device__ __forceinline__ void cp_wait() { asm volatile("cp.async.wait_group %0;" :: "n"(NN)); }

__device__ __forceinline__ void mma_tf32(float c[4], float a0, float a1, float a2, float a3,
                                         float b0, float b1) {
    asm volatile(
        "mma.sync.aligned.m16n8k8.row.col.f32.tf32.tf32.f32 "
        "{%0,%1,%2,%3}, {%4,%5,%6,%7}, {%8,%9}, {%0,%1,%2,%3};"
        : "+f"(c[0]), "+f"(c[1]), "+f"(c[2]), "+f"(c[3])
        : "r"(__float_as_uint(a0)), "r"(__float_as_uint(a1)),
          "r"(__float_as_uint(a2)), "r"(__float_as_uint(a3)),
          "r"(__float_as_uint(b0)), "r"(__float_as_uint(b1)));
}

// ---------------------------------------------------------------------------
// Kernel 1: XW = X @ W1 -> g_XW [B,N,32] fp32.
// 512 threads: 16 warps = 8 m16-positions x 2 n16-halves.
// grid (XMB, B_).
// ---------------------------------------------------------------------------
__global__ __launch_bounds__(512) void xw_kernel(const float* __restrict__ Xg,
                                                 const float* __restrict__ W1) {
    extern __shared__ __align__(16) float smem[];
    float* As = smem;
    float* Bs = smem + XS_ * XAPITCH;

    const int tid = threadIdx.x;
    const int b = blockIdx.y;
    const int mb = blockIdx.x;
    const int w = tid >> 5;
    const int lane = tid & 31;
    const int g = lane >> 2;
    const int t = lane & 3;
    const int mq = w >> 1;       // m16 position 0..7
    const int nh = w & 1;        // n16 half

    const float* Ab = Xg + ((size_t)b * N_ + (size_t)mb * XBM) * F_;

    float acc[2][4];
#pragma unroll
    for (int nt = 0; nt < 2; nt++)
#pragma unroll
        for (int i = 0; i < 4; i++) acc[nt][i] = 0.f;

    auto stage = [&](int kt, int p) {
        const int k0s = kt * BK;
#pragma unroll
        for (int i = 0; i < 2; i++) {            // 1024 A chunks, 2/thread
            int c = tid + i * 512;
            int row = c >> 3, kq = c & 7;
            cp16(&As[p * XAPITCH + row * ASTR + kq * 4],
                 Ab + (size_t)row * F_ + k0s + kq * 4);
        }
        if (tid < 256) {                          // 256 B chunks
            int kk = tid >> 3, j = tid & 7;
            cp16(&Bs[p * BPITCH + kk * BSTR + j * 4],
                 W1 + (size_t)(k0s + kk) * HID_ + j * 4);
        }
    };

#pragma unroll
    for (int s = 0; s < XS_ - 1; s++) { stage(s, s); cp_commit(); }

#pragma unroll
    for (int kt = 0; kt < XNKT; kt++) {
        cp_wait<XS_ - 2>();
        __syncthreads();
        if (kt + XS_ - 1 < XNKT) stage(kt + XS_ - 1, (kt + XS_ - 1) % XS_);
        cp_commit();

        const int p = kt % XS_;
        const float* Asp = &As[p * XAPITCH];
        const float* Bsp = &Bs[p * BPITCH];
#pragma unroll
        for (int kc = 0; kc < 4; kc++) {
            const int kb = kc * 8;
            const int r0 = mq * 16 + g;
            float a0 = Asp[(r0)     * ASTR + kb + t];
            float a1 = Asp[(r0 + 8) * ASTR + kb + t];
            float a2 = Asp[(r0)     * ASTR + kb + t + 4];
            float a3 = Asp[(r0 + 8) * ASTR + kb + t + 4];
#pragma unroll
            for (int nt = 0; nt < 2; nt++) {
                float bb0 = Bsp[(kb + t)     * BSTR + (nh * 2 + nt) * 8 + g];
                float bb1 = Bsp[(kb + t + 4) * BSTR + (nh * 2 + nt) * 8 + g];
                mma_tf32(acc[nt], a0, a1, a2, a3, bb0, bb1);
            }
        }
    }

    const size_t base = (size_t)b * N_ + (size_t)mb * XBM + mq * 16;
#pragma unroll
    for (int nt = 0; nt < 2; nt++) {
        const int c0 = nh * 16 + nt * 8 + 2 * t;
        float2 v0 = make_float2(acc[nt][0], acc[nt][1]);
        float2 v1 = make_float2(acc[nt][2], acc[nt][3]);
        *reinterpret_cast<float2*>(&g_XW[(base + g)     * HID_ + c0]) = v0;
        *reinterpret_cast<float2*>(&g_XW[(base + g + 8) * HID_ + c0]) = v1;
    }
}

// ---------------------------------------------------------------------------
// Kernel 2: Y = filtre @ XW per batch (M=2048,K=2048,N=32), tf32 mma,
// relu(Y+b1), deterministic column-sum -> g_part[b][mb][32].
// 512 threads: 16 warps = 8 m32-positions x 2 n16-halves (mf=2, nt=2).
// 5-stage single-sync cp.async pipeline. grid (MB2, B_) = 128 blocks.
// ---------------------------------------------------------------------------
__global__ __launch_bounds__(512) void main_kernel(const float* __restrict__ A,
                                                   const float* __restrict__ b1) {
    extern __shared__ __align__(16) float smem[];
    float* As = smem;                        // [S2][BM2*ASTR]
    float* Bs = smem + S2 * A2PITCH;         // [S2][BK*BSTR]
    __shared__ float red[16 * 16];

    const int tid = threadIdx.x;
    const int b = blockIdx.y;
    const int mb = blockIdx.x;
    const int w = tid >> 5;
    const int lane = tid & 31;
    const int g = lane >> 2;
    const int t = lane & 3;
    const int mq = w >> 1;       // m32 position 0..7
    const int nh = w & 1;        // n16 half

    const float* Ab = A + ((size_t)b * N_ + (size_t)mb * BM2) * N_;
    const float* Bb = g_XW + (size_t)b * N_ * HID_;

    float acc[2][2][4];
#pragma unroll
    for (int mf = 0; mf < 2; mf++)
#pragma unroll
        for (int nt = 0; nt < 2; nt++)
#pragma unroll
            for (int i = 0; i < 4; i++) acc[mf][nt][i] = 0.f;

    auto stage = [&](int kt, int p) {
        const int k0s = kt * BK;
#pragma unroll
        for (int i = 0; i < 4; i++) {             // 2048 A chunks, 4/thread
            int c = tid + i * 512;
            int row = c >> 3, kq = c & 7;
            cp16(&As[p * A2PITCH + row * ASTR + kq * 4],
                 Ab + (size_t)row * N_ + k0s + kq * 4);
        }
        if (tid < 256) {                          // 256 B chunks
            int kk = tid >> 3, j = tid & 7;
            cp16(&Bs[p * BPITCH + kk * BSTR + j * 4],
                 Bb + (size_t)(k0s + kk) * HID_ + j * 4);
        }
    };

#pragma unroll
    for (int s = 0; s < S2 - 1; s++) { stage(s, s); cp_commit(); }

    for (int kt = 0; kt < NKT; kt++) {
        cp_wait<S2 - 2>();          // tile kt landed
        __syncthreads();            // reads of buffer (kt-1)%S2 are done
        if (kt + S2 - 1 < NKT) stage(kt + S2 - 1, (kt + S2 - 1) % S2);
        cp_commit();                // uniform group accounting

        const int p = kt % S2;
        const float* Asp = &As[p * A2PITCH];
        const float* Bsp = &Bs[p * BPITCH];
#pragma unroll
        for (int kc = 0; kc < 4; kc++) {
            const int kb = kc * 8;
            float bb0[2], bb1[2];
#pragma unroll
            for (int nt = 0; nt < 2; nt++) {
                bb0[nt] = Bsp[(kb + t)     * BSTR + (nh * 2 + nt) * 8 + g];
                bb1[nt] = Bsp[(kb + t + 4) * BSTR + (nh * 2 + nt) * 8 + g];
            }
#pragma unroll
            for (int mf = 0; mf < 2; mf++) {
                const int r0 = mq * 32 + mf * 16 + g;
                float a0 = Asp[(r0)     * ASTR + kb + t];
                float a1 = Asp[(r0 + 8) * ASTR + kb + t];
                float a2 = Asp[(r0)     * ASTR + kb + t + 4];
                float a3 = Asp[(r0 + 8) * ASTR + kb + t + 4];
#pragma unroll
                for (int nt = 0; nt < 2; nt++)
                    mma_tf32(acc[mf][nt], a0, a1, a2, a3, bb0[nt], bb1[nt]);
            }
        }
    }

    // Epilogue: +b1, relu, deterministic column-sum over this block's 256 rows.
    float2 csum[2];
#pragma unroll
    for (int nt = 0; nt < 2; nt++) {
        float2 bb = *reinterpret_cast<const float2*>(b1 + nh * 16 + nt * 8 + 2 * t);
        float v0 = 0.f, v1 = 0.f;
#pragma unroll
        for (int mf = 0; mf < 2; mf++) {
            v0 += fmaxf(acc[mf][nt][0] + bb.x, 0.f) + fmaxf(acc[mf][nt][2] + bb.x, 0.f);
            v1 += fmaxf(acc[mf][nt][1] + bb.y, 0.f) + fmaxf(acc[mf][nt][3] + bb.y, 0.f);
        }
        csum[nt] = make_float2(v0, v1);
    }
#pragma unroll
    for (int nt = 0; nt < 2; nt++) {
#pragma unroll
        for (int off = 16; off >= 4; off >>= 1) {
            csum[nt].x += __shfl_xor_sync(0xffffffffu, csum[nt].x, off);
            csum[nt].y += __shfl_xor_sync(0xffffffffu, csum[nt].y, off);
        }
    }
    __syncthreads();
    if (g == 0) {                 // lanes 0..3 hold col sums for this warp's 16 cols
#pragma unroll
        for (int nt = 0; nt < 2; nt++) {
            red[w * 16 + nt * 8 + 2 * t + 0] = csum[nt].x;
            red[w * 16 + nt * 8 + 2 * t + 1] = csum[nt].y;
        }
    }
    __syncthreads();
    if (tid < HID_) {
        const int nh2 = tid >> 4, cl = tid & 15;
        float s = 0.f;
#pragma unroll
        for (int mq2 = 0; mq2 < 8; mq2++)
            s += red[(mq2 * 2 + nh2) * 16 + cl];
        g_part[((size_t)b * MB2 + mb) * HID_ + tid] = s;
    }
}

// ---------------------------------------------------------------------------
// Kernel 3: Xp = sum(partials); h = relu(Xp@Wd+bd); out = softmax(h@Wc+bc)
// ---------------------------------------------------------------------------
__global__ __launch_bounds__(512) void head_kernel(const float* __restrict__ Wd,
                                                   const float* __restrict__ bd,
                                                   const float* __restrict__ Wc,
                                                   const float* __restrict__ bc,
                                                   float* __restrict__ out) {
    __shared__ float xp[HID_];
    __shared__ float hbuf[FC_];
    __shared__ float logits[C_];
    const int b = blockIdx.x;
    const int tid = threadIdx.x;

    if (tid < HID_) {
        float s = 0.f;
#pragma unroll
        for (int mb = 0; mb < MB2; mb++)
            s += g_part[((size_t)b * MB2 + mb) * HID_ + tid];
        xp[tid] = s;
    }
    __syncthreads();

    {
        float acc = bd[tid];
#pragma unroll
        for (int h = 0; h < HID_; h++)
            acc = fmaf(xp[h], Wd[h * FC_ + tid], acc);
        hbuf[tid] = fmaxf(acc, 0.f);
    }
    __syncthreads();

    if (tid < C_) {
        float acc = bc[tid];
        for (int f = 0; f < FC_; f++)
            acc = fmaf(hbuf[f], Wc[f * C_ + tid], acc);
        logits[tid] = acc;
    }
    __syncthreads();

    if (tid == 0) {
        float mx = logits[0];
#pragma unroll
        for (int c = 1; c < C_; c++) mx = fmaxf(mx, logits[c]);
        float e[C_];
        float sum = 0.f;
#pragma unroll
        for (int c = 0; c < C_; c++) { e[c] = expf(logits[c] - mx); sum += e[c]; }
        float inv = 1.f / sum;
#pragma unroll
        for (int c = 0; c < C_; c++) out[b * C_ + c] = e[c] * inv;
    }
}

// ---------------------------------------------------------------------------
extern "C" void kernel_launch(void* const* d_in, const int* in_sizes, int n_in,
                              void* d_out, int out_size) {
    const float* filtre = (const float*)d_in[0];
    const float* X      = (const float*)d_in[1];
    // d_in[2] node_indicator: unused by the reference math
    const float* W1     = (const float*)d_in[3];
    const float* b1     = (const float*)d_in[4];
    // d_in[5] Ws: dead (softmax over size-1 cluster axis == 1)
    const float* Wd     = (const float*)d_in[6];
    const float* bd     = (const float*)d_in[7];
    const float* Wc     = (const float*)d_in[8];
    const float* bc     = (const float*)d_in[9];
    float* out = (float*)d_out;

    // Idempotent, non-stream host calls (no allocation).
    cudaFuncSetAttribute(xw_kernel,
                         cudaFuncAttributeMaxDynamicSharedMemorySize, XW_SMEM);
    cudaFuncSetAttribute(main_kernel,
                         cudaFuncAttributeMaxDynamicSharedMemorySize, MAIN_SMEM);

    xw_kernel  <<<dim3(XMB, B_), 512, XW_SMEM  >>>(X, W1);
    main_kernel<<<dim3(MB2, B_), 512, MAIN_SMEM>>>(filtre, b1);
    head_kernel<<<B_, FC_>>>(Wd, bd, Wc, bc, out);
}

// round 16
// speedup vs baseline: 1.0004x; 1.0004x over previous
#include <cuda_runtime.h>
#include <cstdint>

#define B_   16
#define N_   2048
#define F_   128
#define HID_ 32
#define FC_  512
#define C_   10

// ---- xw kernel (tf32 mma.sync, 256 threads, R14-proven) ----
#define XBM  128
#define XBK  32
#define XMB  (N_ / XBM)    // 16
#define XS_  3
#define XNKT (F_ / XBK)    // 4
#define XASTR 36
#define XBSTR 40
#define XAPITCH (XBM * XASTR)
#define XBPITCH (XBK * XBSTR)
#define XW_SMEM ((XS_ * XAPITCH + XS_ * XBPITCH) * 4)

// ---- main kernel (tf32 mma.sync, BM=256, BK=64, S=2) ----
#define BM2  256
#define BK2  64
#define MB2  (N_ / BM2)    // 8
#define NKT2 (N_ / BK2)    // 32
#define ASTR2 68           // 64 + 4 pad: frag bank = 4g + t (+kb), conflict-free
#define BSTR2 40
#define A2PITCH (BM2 * ASTR2)   // 17408 floats
#define B2PITCH (BK2 * BSTR2)   // 2560 floats
#define MAIN_SMEM (2 * (A2PITCH + B2PITCH) * 4)   // ~160 KB

// Scratch (no cudaMalloc allowed)
__device__ float g_XW[B_ * N_ * HID_];         // X @ W1  [B,N,32] fp32
__device__ float g_part[B_ * MB2 * HID_];      // per-block relu column sums

// ---------------- helpers ----------------
__device__ __forceinline__ void cp16(float* dst, const float* src) {
    unsigned s = (unsigned)__cvta_generic_to_shared(dst);
    asm volatile("cp.async.cg.shared.global [%0], [%1], 16;" :: "r"(s), "l"(src));
}
__device__ __forceinline__ void cp_commit() { asm volatile("cp.async.commit_group;"); }
template <int NN>
__device__ __forceinline__ void cp_wait() { asm volatile("cp.async.wait_group %0;" :: "n"(NN)); }

__device__ __forceinline__ void mma_tf32(float c[4], float a0, float a1, float a2, float a3,
                                         float b0, float b1) {
    asm volatile(
        "mma.sync.aligned.m16n8k8.row.col.f32.tf32.tf32.f32 "
        "{%0,%1,%2,%3}, {%4,%5,%6,%7}, {%8,%9}, {%0,%1,%2,%3};"
        : "+f"(c[0]), "+f"(c[1]), "+f"(c[2]), "+f"(c[3])
        : "r"(__float_as_uint(a0)), "r"(__float_as_uint(a1)),
          "r"(__float_as_uint(a2)), "r"(__float_as_uint(a3)),
          "r"(__float_as_uint(b0)), "r"(__float_as_uint(b1)));
}

// ---------------------------------------------------------------------------
// Kernel 1: XW = X @ W1 -> g_XW [B,N,32] fp32. (R14-proven, 256 threads)
// ---------------------------------------------------------------------------
__global__ __launch_bounds__(256) void xw_kernel(const float* __restrict__ Xg,
                                                 const float* __restrict__ W1) {
    extern __shared__ __align__(16) float smem[];
    float* As = smem;
    float* Bs = smem + XS_ * XAPITCH;

    const int tid = threadIdx.x;
    const int b = blockIdx.y;
    const int mb = blockIdx.x;
    const int w = tid >> 5;
    const int lane = tid & 31;
    const int g = lane >> 2;
    const int t = lane & 3;

    const float* Ab = Xg + ((size_t)b * N_ + (size_t)mb * XBM) * F_;

    float acc[4][4];
#pragma unroll
    for (int nt = 0; nt < 4; nt++)
#pragma unroll
        for (int i = 0; i < 4; i++) acc[nt][i] = 0.f;

    auto stage = [&](int kt, int p) {
        const int k0s = kt * XBK;
#pragma unroll
        for (int i = 0; i < 4; i++) {
            int c = tid + i * 256;
            int row = c >> 3, kq = c & 7;
            cp16(&As[p * XAPITCH + row * XASTR + kq * 4],
                 Ab + (size_t)row * F_ + k0s + kq * 4);
        }
        {
            int kk = tid >> 3, j = tid & 7;
            cp16(&Bs[p * XBPITCH + kk * XBSTR + j * 4],
                 W1 + (size_t)(k0s + kk) * HID_ + j * 4);
        }
    };

#pragma unroll
    for (int s = 0; s < XS_ - 1; s++) { stage(s, s); cp_commit(); }

#pragma unroll
    for (int kt = 0; kt < XNKT; kt++) {
        cp_wait<XS_ - 2>();
        __syncthreads();
        if (kt + XS_ - 1 < XNKT) stage(kt + XS_ - 1, (kt + XS_ - 1) % XS_);
        cp_commit();

        const int p = kt % XS_;
        const float* Asp = &As[p * XAPITCH];
        const float* Bsp = &Bs[p * XBPITCH];
#pragma unroll
        for (int kc = 0; kc < 4; kc++) {
            const int kb = kc * 8;
            float a0 = Asp[(w * 16 + g)     * XASTR + kb + t];
            float a1 = Asp[(w * 16 + g + 8) * XASTR + kb + t];
            float a2 = Asp[(w * 16 + g)     * XASTR + kb + t + 4];
            float a3 = Asp[(w * 16 + g + 8) * XASTR + kb + t + 4];
#pragma unroll
            for (int nt = 0; nt < 4; nt++) {
                float bb0 = Bsp[(kb + t)     * XBSTR + nt * 8 + g];
                float bb1 = Bsp[(kb + t + 4) * XBSTR + nt * 8 + g];
                mma_tf32(acc[nt], a0, a1, a2, a3, bb0, bb1);
            }
        }
    }

    const size_t base = (size_t)b * N_ + (size_t)mb * XBM + w * 16;
#pragma unroll
    for (int nt = 0; nt < 4; nt++) {
        float2 v0 = make_float2(acc[nt][0], acc[nt][1]);
        float2 v1 = make_float2(acc[nt][2], acc[nt][3]);
        *reinterpret_cast<float2*>(&g_XW[(base + g)     * HID_ + nt * 8 + 2 * t]) = v0;
        *reinterpret_cast<float2*>(&g_XW[(base + g + 8) * HID_ + nt * 8 + 2 * t]) = v1;
    }
}

// ---------------------------------------------------------------------------
// Kernel 2: Y = filtre @ XW per batch (M=2048,K=2048,N=32), tf32 mma,
// relu(Y+b1), deterministic column-sum -> g_part[b][mb][32].
// BK=64 (256B contiguous per row per tile), BM=256, S=2 double buffer,
// 256 threads: 8 warps of m32 x n32. grid (MB2, B_) = 128 blocks, one wave.
// ---------------------------------------------------------------------------
__global__ __launch_bounds__(256) void main_kernel(const float* __restrict__ A,
                                                   const float* __restrict__ b1) {
    extern __shared__ __align__(16) float smem[];
    float* As = smem;                         // [2][BM2*ASTR2]
    float* Bs = smem + 2 * A2PITCH;           // [2][BK2*BSTR2]
    __shared__ float red[8 * HID_];

    const int tid = threadIdx.x;
    const int b = blockIdx.y;
    const int mb = blockIdx.x;
    const int w = tid >> 5;
    const int lane = tid & 31;
    const int g = lane >> 2;
    const int t = lane & 3;

    const float* Ab = A + ((size_t)b * N_ + (size_t)mb * BM2) * N_;
    const float* Bb = g_XW + (size_t)b * N_ * HID_;

    float acc[2][4][4];
#pragma unroll
    for (int mf = 0; mf < 2; mf++)
#pragma unroll
        for (int nt = 0; nt < 4; nt++)
#pragma unroll
            for (int i = 0; i < 4; i++) acc[mf][nt][i] = 0.f;

    auto stage = [&](int kt, int p) {
        const int k0s = kt * BK2;
        // A: 256 rows x 16 chunks (16B) = 4096 chunks, 16/thread.
        // threads 0-15 cover row 0's 256B contiguously -> large DRAM grain.
#pragma unroll
        for (int i = 0; i < 16; i++) {
            int c = tid + i * 256;
            int row = c >> 4, kq = c & 15;
            cp16(&As[p * A2PITCH + row * ASTR2 + kq * 4],
                 Ab + (size_t)row * N_ + k0s + kq * 4);
        }
        // B: 64 k-rows x 8 chunks = 512 chunks, 2/thread.
#pragma unroll
        for (int i = 0; i < 2; i++) {
            int c = tid + i * 256;
            int kk = c >> 3, j = c & 7;
            cp16(&Bs[p * B2PITCH + kk * BSTR2 + j * 4],
                 Bb + (size_t)(k0s + kk) * HID_ + j * 4);
        }
    };

    stage(0, 0); cp_commit();

    for (int kt = 0; kt < NKT2; kt++) {
        cp_wait<0>();               // tile kt landed (kt+1 not yet committed)
        __syncthreads();            // all reads of buffer (kt-1)&1 are done
        if (kt + 1 < NKT2) { stage(kt + 1, (kt + 1) & 1); cp_commit(); }

        const int p = kt & 1;
        const float* Asp = &As[p * A2PITCH];
        const float* Bsp = &Bs[p * B2PITCH];
#pragma unroll
        for (int kc = 0; kc < 8; kc++) {
            const int kb = kc * 8;
            float bb0[4], bb1[4];
#pragma unroll
            for (int nt = 0; nt < 4; nt++) {
                bb0[nt] = Bsp[(kb + t)     * BSTR2 + nt * 8 + g];
                bb1[nt] = Bsp[(kb + t + 4) * BSTR2 + nt * 8 + g];
            }
#pragma unroll
            for (int mf = 0; mf < 2; mf++) {
                const int r0 = w * 32 + mf * 16 + g;
                float a0 = Asp[(r0)     * ASTR2 + kb + t];
                float a1 = Asp[(r0 + 8) * ASTR2 + kb + t];
                float a2 = Asp[(r0)     * ASTR2 + kb + t + 4];
                float a3 = Asp[(r0 + 8) * ASTR2 + kb + t + 4];
#pragma unroll
                for (int nt = 0; nt < 4; nt++)
                    mma_tf32(acc[mf][nt], a0, a1, a2, a3, bb0[nt], bb1[nt]);
            }
        }
    }

    // Epilogue: +b1, relu, deterministic column-sum over this block's 256 rows.
    float2 csum[4];
#pragma unroll
    for (int nt = 0; nt < 4; nt++) {
        float2 bb = *reinterpret_cast<const float2*>(b1 + nt * 8 + 2 * t);
        float v0 = 0.f, v1 = 0.f;
#pragma unroll
        for (int mf = 0; mf < 2; mf++) {
            v0 += fmaxf(acc[mf][nt][0] + bb.x, 0.f) + fmaxf(acc[mf][nt][2] + bb.x, 0.f);
            v1 += fmaxf(acc[mf][nt][1] + bb.y, 0.f) + fmaxf(acc[mf][nt][3] + bb.y, 0.f);
        }
        csum[nt] = make_float2(v0, v1);
    }
#pragma unroll
    for (int nt = 0; nt < 4; nt++) {
#pragma unroll
        for (int off = 16; off >= 4; off >>= 1) {
            csum[nt].x += __shfl_xor_sync(0xffffffffu, csum[nt].x, off);
            csum[nt].y += __shfl_xor_sync(0xffffffffu, csum[nt].y, off);
        }
    }
    __syncthreads();
    if (g == 0) {
#pragma unroll
        for (int nt = 0; nt < 4; nt++) {
            red[w * HID_ + nt * 8 + 2 * t + 0] = csum[nt].x;
            red[w * HID_ + nt * 8 + 2 * t + 1] = csum[nt].y;
        }
    }
    __syncthreads();
    if (tid < HID_) {
        float s = 0.f;
#pragma unroll
        for (int ww = 0; ww < 8; ww++) s += red[ww * HID_ + tid];
        g_part[((size_t)b * MB2 + mb) * HID_ + tid] = s;
    }
}

// ---------------------------------------------------------------------------
// Kernel 3: Xp = sum(partials); h = relu(Xp@Wd+bd); out = softmax(h@Wc+bc)
// ---------------------------------------------------------------------------
__global__ __launch_bounds__(512) void head_kernel(const float* __restrict__ Wd,
                                                   const float* __restrict__ bd,
                                                   const float* __restrict__ Wc,
                                                   const float* __restrict__ bc,
                                                   float* __restrict__ out) {
    __shared__ float xp[HID_];
    __shared__ float hbuf[FC_];
    __shared__ float logits[C_];
    const int b = blockIdx.x;
    const int tid = threadIdx.x;

    if (tid < HID_) {
        float s = 0.f;
#pragma unroll
        for (int mb = 0; mb < MB2; mb++)
            s += g_part[((size_t)b * MB2 + mb) * HID_ + tid];
        xp[tid] = s;
    }
    __syncthreads();

    {
        float acc = bd[tid];
#pragma unroll
        for (int h = 0; h < HID_; h++)
            acc = fmaf(xp[h], Wd[h * FC_ + tid], acc);
        hbuf[tid] = fmaxf(acc, 0.f);
    }
    __syncthreads();

    if (tid < C_) {
        float acc = bc[tid];
        for (int f = 0; f < FC_; f++)
            acc = fmaf(hbuf[f], Wc[f * C_ + tid], acc);
        logits[tid] = acc;
    }
    __syncthreads();

    if (tid == 0) {
        float mx = logits[0];
#pragma unroll
        for (int c = 1; c < C_; c++) mx = fmaxf(mx, logits[c]);
        float e[C_];
        float sum = 0.f;
#pragma unroll
        for (int c = 0; c < C_; c++) { e[c] = expf(logits[c] - mx); sum += e[c]; }
        float inv = 1.f / sum;
#pragma unroll
        for (int c = 0; c < C_; c++) out[b * C_ + c] = e[c] * inv;
    }
}

// ---------------------------------------------------------------------------
extern "C" void kernel_launch(void* const* d_in, const int* in_sizes, int n_in,
                              void* d_out, int out_size) {
    const float* filtre = (const float*)d_in[0];
    const float* X      = (const float*)d_in[1];
    // d_in[2] node_indicator: unused by the reference math
    const float* W1     = (const float*)d_in[3];
    const float* b1     = (const float*)d_in[4];
    // d_in[5] Ws: dead (softmax over size-1 cluster axis == 1)
    const float* Wd     = (const float*)d_in[6];
    const float* bd     = (const float*)d_in[7];
    const float* Wc     = (const float*)d_in[8];
    const float* bc     = (const float*)d_in[9];
    float* out = (float*)d_out;

    // Idempotent, non-stream host calls (no allocation).
    cudaFuncSetAttribute(xw_kernel,
                         cudaFuncAttributeMaxDynamicSharedMemorySize, XW_SMEM);
    cudaFuncSetAttribute(main_kernel,
                         cudaFuncAttributeMaxDynamicSharedMemorySize, MAIN_SMEM);

    xw_kernel  <<<dim3(XMB, B_), 256, XW_SMEM  >>>(X, W1);
    main_kernel<<<dim3(MB2, B_), 256, MAIN_SMEM>>>(filtre, b1);
    head_kernel<<<B_, FC_>>>(Wd, bd, Wc, bc, out);
}

// round 17
// speedup vs baseline: 1.1019x; 1.1015x over previous
#include <cuda_runtime.h>
#include <cstdint>

#define B_   16
#define N_   2048
#define F_   128
#define HID_ 32
#define FC_  512
#define C_   10

// ---- xw kernel (tf32 mma.sync, 128 threads, XBM=64, 512 blocks) ----
#define XBM  64
#define XBK  32
#define XMB  (N_ / XBM)    // 32
#define XS_  3
#define XNKT (F_ / XBK)    // 4
#define XASTR 36
#define XBSTR 40
#define XAPITCH (XBM * XASTR)
#define XBPITCH (XBK * XBSTR)
#define XW_SMEM ((XS_ * XAPITCH + XS_ * XBPITCH) * 4)    // ~43 KB

// ---- main kernel (tf32 mma.sync, BM=256, S=5, single-sync; R13/R14-proven) ----
#define BM2  256
#define BK   32
#define MB2  (N_ / BM2)    // 8
#define NKT  (N_ / BK)     // 64
#define S2   5
#define ASTR 36
#define BSTR 40
#define A2PITCH (BM2 * ASTR)
#define BPITCH  (BK * BSTR)
#define MAIN_SMEM ((S2 * A2PITCH + S2 * BPITCH) * 4)     // ~210 KB

// Scratch (no cudaMalloc allowed)
__device__ float g_XW[B_ * N_ * HID_];         // X @ W1  [B,N,32] fp32
__device__ float g_part[B_ * MB2 * HID_];      // per-block relu column sums

// ---------------- helpers ----------------
__device__ __forceinline__ void cp16(float* dst, const float* src) {
    unsigned s = (unsigned)__cvta_generic_to_shared(dst);
    asm volatile("cp.async.cg.shared.global [%0], [%1], 16;" :: "r"(s), "l"(src));
}
// A-staging variant: prefetch the surrounding 256B into L2 (next k-tile's bytes).
__device__ __forceinline__ void cp16_pf(float* dst, const float* src) {
    unsigned s = (unsigned)__cvta_generic_to_shared(dst);
    asm volatile("cp.async.cg.shared.global.L2::256B [%0], [%1], 16;" :: "r"(s), "l"(src));
}
__device__ __forceinline__ void cp_commit() { asm volatile("cp.async.commit_group;"); }
template <int NN>
__device__ __forceinline__ void cp_wait() { asm volatile("cp.async.wait_group %0;" :: "n"(NN)); }

__device__ __forceinline__ void mma_tf32(float c[4], float a0, float a1, float a2, float a3,
                                         float b0, float b1) {
    asm volatile(
        "mma.sync.aligned.m16n8k8.row.col.f32.tf32.tf32.f32 "
        "{%0,%1,%2,%3}, {%4,%5,%6,%7}, {%8,%9}, {%0,%1,%2,%3};"
        : "+f"(c[0]), "+f"(c[1]), "+f"(c[2]), "+f"(c[3])
        : "r"(__float_as_uint(a0)), "r"(__float_as_uint(a1)),
          "r"(__float_as_uint(a2)), "r"(__float_as_uint(a3)),
          "r"(__float_as_uint(b0)), "r"(__float_as_uint(b1)));
}

// ---------------------------------------------------------------------------
// Kernel 1: XW = X @ W1 -> g_XW [B,N,32] fp32.
// 128 threads, 4 warps (each m16 x n32), XBM=64 -> 512 blocks.
// grid (XMB, B_).
// ---------------------------------------------------------------------------
__global__ __launch_bounds__(128) void xw_kernel(const float* __restrict__ Xg,
                                                 const float* __restrict__ W1) {
    extern __shared__ __align__(16) float smem[];
    float* As = smem;
    float* Bs = smem + XS_ * XAPITCH;

    const int tid = threadIdx.x;
    const int b = blockIdx.y;
    const int mb = blockIdx.x;
    const int w = tid >> 5;
    const int lane = tid & 31;
    const int g = lane >> 2;
    const int t = lane & 3;

    const float* Ab = Xg + ((size_t)b * N_ + (size_t)mb * XBM) * F_;

    float acc[4][4];
#pragma unroll
    for (int nt = 0; nt < 4; nt++)
#pragma unroll
        for (int i = 0; i < 4; i++) acc[nt][i] = 0.f;

    auto stage = [&](int kt, int p) {
        const int k0s = kt * XBK;
#pragma unroll
        for (int i = 0; i < 4; i++) {            // 512 A chunks, 4/thread
            int c = tid + i * 128;
            int row = c >> 3, kq = c & 7;
            cp16_pf(&As[p * XAPITCH + row * XASTR + kq * 4],
                    Ab + (size_t)row * F_ + k0s + kq * 4);
        }
#pragma unroll
        for (int i = 0; i < 2; i++) {            // 256 B chunks, 2/thread
            int c = tid + i * 128;
            int kk = c >> 3, j = c & 7;
            cp16(&Bs[p * XBPITCH + kk * XBSTR + j * 4],
                 W1 + (size_t)(k0s + kk) * HID_ + j * 4);
        }
    };

#pragma unroll
    for (int s = 0; s < XS_ - 1; s++) { stage(s, s); cp_commit(); }

#pragma unroll
    for (int kt = 0; kt < XNKT; kt++) {
        cp_wait<XS_ - 2>();
        __syncthreads();
        if (kt + XS_ - 1 < XNKT) stage(kt + XS_ - 1, (kt + XS_ - 1) % XS_);
        cp_commit();

        const int p = kt % XS_;
        const float* Asp = &As[p * XAPITCH];
        const float* Bsp = &Bs[p * XBPITCH];
#pragma unroll
        for (int kc = 0; kc < 4; kc++) {
            const int kb = kc * 8;
            float a0 = Asp[(w * 16 + g)     * XASTR + kb + t];
            float a1 = Asp[(w * 16 + g + 8) * XASTR + kb + t];
            float a2 = Asp[(w * 16 + g)     * XASTR + kb + t + 4];
            float a3 = Asp[(w * 16 + g + 8) * XASTR + kb + t + 4];
#pragma unroll
            for (int nt = 0; nt < 4; nt++) {
                float bb0 = Bsp[(kb + t)     * XBSTR + nt * 8 + g];
                float bb1 = Bsp[(kb + t + 4) * XBSTR + nt * 8 + g];
                mma_tf32(acc[nt], a0, a1, a2, a3, bb0, bb1);
            }
        }
    }

    const size_t base = (size_t)b * N_ + (size_t)mb * XBM + w * 16;
#pragma unroll
    for (int nt = 0; nt < 4; nt++) {
        float2 v0 = make_float2(acc[nt][0], acc[nt][1]);
        float2 v1 = make_float2(acc[nt][2], acc[nt][3]);
        *reinterpret_cast<float2*>(&g_XW[(base + g)     * HID_ + nt * 8 + 2 * t]) = v0;
        *reinterpret_cast<float2*>(&g_XW[(base + g + 8) * HID_ + nt * 8 + 2 * t]) = v1;
    }
}

// ---------------------------------------------------------------------------
// Kernel 2: Y = filtre @ XW per batch (M=2048,K=2048,N=32), tf32 mma,
// relu(Y+b1), deterministic column-sum -> g_part[b][mb][32].
// BM=256, 8 warps of m32 x n32; 5-stage single-sync cp.async pipeline with
// L2::256B prefetch on A (pulls next k-tile's bytes into L2 at 256B grain).
// grid (MB2, B_) = 128 blocks (one balanced wave).
// ---------------------------------------------------------------------------
__global__ __launch_bounds__(256) void main_kernel(const float* __restrict__ A,
                                                   const float* __restrict__ b1) {
    extern __shared__ __align__(16) float smem[];
    float* As = smem;                        // [S2][BM2*ASTR]
    float* Bs = smem + S2 * A2PITCH;         // [S2][BK*BSTR]
    __shared__ float red[8 * HID_];

    const int tid = threadIdx.x;
    const int b = blockIdx.y;
    const int mb = blockIdx.x;
    const int w = tid >> 5;
    const int lane = tid & 31;
    const int g = lane >> 2;
    const int t = lane & 3;

    const float* Ab = A + ((size_t)b * N_ + (size_t)mb * BM2) * N_;
    const float* Bb = g_XW + (size_t)b * N_ * HID_;

    float acc[2][4][4];
#pragma unroll
    for (int mf = 0; mf < 2; mf++)
#pragma unroll
        for (int nt = 0; nt < 4; nt++)
#pragma unroll
            for (int i = 0; i < 4; i++) acc[mf][nt][i] = 0.f;

    auto stage = [&](int kt, int p) {
        const int k0s = kt * BK;
#pragma unroll
        for (int i = 0; i < 8; i++) {                 // 2048 chunks, 8/thread
            int c = tid + i * 256;
            int row = c >> 3, kq = c & 7;
            cp16_pf(&As[p * A2PITCH + row * ASTR + kq * 4],
                    Ab + (size_t)row * N_ + k0s + kq * 4);
        }
        {
            int kk = tid >> 3, j = tid & 7;
            cp16(&Bs[p * BPITCH + kk * BSTR + j * 4],
                 Bb + (size_t)(k0s + kk) * HID_ + j * 4);
        }
    };

#pragma unroll
    for (int s = 0; s < S2 - 1; s++) { stage(s, s); cp_commit(); }

    for (int kt = 0; kt < NKT; kt++) {
        cp_wait<S2 - 2>();          // tile kt landed
        __syncthreads();            // reads of buffer (kt-1)%S2 are done
        if (kt + S2 - 1 < NKT) stage(kt + S2 - 1, (kt + S2 - 1) % S2);
        cp_commit();                // uniform group accounting

        const int p = kt % S2;
        const float* Asp = &As[p * A2PITCH];
        const float* Bsp = &Bs[p * BPITCH];
#pragma unroll
        for (int kc = 0; kc < 4; kc++) {
            const int kb = kc * 8;
            float bb0[4], bb1[4];
#pragma unroll
            for (int nt = 0; nt < 4; nt++) {
                bb0[nt] = Bsp[(kb + t)     * BSTR + nt * 8 + g];
                bb1[nt] = Bsp[(kb + t + 4) * BSTR + nt * 8 + g];
            }
#pragma unroll
            for (int mf = 0; mf < 2; mf++) {
                const int r0 = w * 32 + mf * 16 + g;
                float a0 = Asp[(r0)     * ASTR + kb + t];
                float a1 = Asp[(r0 + 8) * ASTR + kb + t];
                float a2 = Asp[(r0)     * ASTR + kb + t + 4];
                float a3 = Asp[(r0 + 8) * ASTR + kb + t + 4];
#pragma unroll
                for (int nt = 0; nt < 4; nt++)
                    mma_tf32(acc[mf][nt], a0, a1, a2, a3, bb0[nt], bb1[nt]);
            }
        }
    }

    // Epilogue: +b1, relu, deterministic column-sum over this block's 256 rows.
    float2 csum[4];
#pragma unroll
    for (int nt = 0; nt < 4; nt++) {
        float2 bb = *reinterpret_cast<const float2*>(b1 + nt * 8 + 2 * t);
        float v0 = 0.f, v1 = 0.f;
#pragma unroll
        for (int mf = 0; mf < 2; mf++) {
            v0 += fmaxf(acc[mf][nt][0] + bb.x, 0.f) + fmaxf(acc[mf][nt][2] + bb.x, 0.f);
            v1 += fmaxf(acc[mf][nt][1] + bb.y, 0.f) + fmaxf(acc[mf][nt][3] + bb.y, 0.f);
        }
        csum[nt] = make_float2(v0, v1);
    }
#pragma unroll
    for (int nt = 0; nt < 4; nt++) {
#pragma unroll
        for (int off = 16; off >= 4; off >>= 1) {
            csum[nt].x += __shfl_xor_sync(0xffffffffu, csum[nt].x, off);
            csum[nt].y += __shfl_xor_sync(0xffffffffu, csum[nt].y, off);
        }
    }
    __syncthreads();
    if (g == 0) {
#pragma unroll
        for (int nt = 0; nt < 4; nt++) {
            red[w * HID_ + nt * 8 + 2 * t + 0] = csum[nt].x;
            red[w * HID_ + nt * 8 + 2 * t + 1] = csum[nt].y;
        }
    }
    __syncthreads();
    if (tid < HID_) {
        float s = 0.f;
#pragma unroll
        for (int ww = 0; ww < 8; ww++) s += red[ww * HID_ + tid];
        g_part[((size_t)b * MB2 + mb) * HID_ + tid] = s;
    }
}

// ---------------------------------------------------------------------------
// Kernel 3: Xp = sum(partials); h = relu(Xp@Wd+bd); out = softmax(h@Wc+bc)
// ---------------------------------------------------------------------------
__global__ __launch_bounds__(512) void head_kernel(const float* __restrict__ Wd,
                                                   const float* __restrict__ bd,
                                                   const float* __restrict__ Wc,
                                                   const float* __restrict__ bc,
                                                   float* __restrict__ out) {
    __shared__ float xp[HID_];
    __shared__ float hbuf[FC_];
    __shared__ float logits[C_];
    const int b = blockIdx.x;
    const int tid = threadIdx.x;

    if (tid < HID_) {
        float s = 0.f;
#pragma unroll
        for (int mb = 0; mb < MB2; mb++)
            s += g_part[((size_t)b * MB2 + mb) * HID_ + tid];
        xp[tid] = s;
    }
    __syncthreads();

    {
        float acc = bd[tid];
#pragma unroll
        for (int h = 0; h < HID_; h++)
            acc = fmaf(xp[h], Wd[h * FC_ + tid], acc);
        hbuf[tid] = fmaxf(acc, 0.f);
    }
    __syncthreads();

    if (tid < C_) {
        float acc = bc[tid];
        for (int f = 0; f < FC_; f++)
            acc = fmaf(hbuf[f], Wc[f * C_ + tid], acc);
        logits[tid] = acc;
    }
    __syncthreads();

    if (tid == 0) {
        float mx = logits[0];
#pragma unroll
        for (int c = 1; c < C_; c++) mx = fmaxf(mx, logits[c]);
        float e[C_];
        float sum = 0.f;
#pragma unroll
        for (int c = 0; c < C_; c++) { e[c] = expf(logits[c] - mx); sum += e[c]; }
        float inv = 1.f / sum;
#pragma unroll
        for (int c = 0; c < C_; c++) out[b * C_ + c] = e[c] * inv;
    }
}

// ---------------------------------------------------------------------------
extern "C" void kernel_launch(void* const* d_in, const int* in_sizes, int n_in,
                              void* d_out, int out_size) {
    const float* filtre = (const float*)d_in[0];
    const float* X      = (const float*)d_in[1];
    // d_in[2] node_indicator: unused by the reference math
    const float* W1     = (const float*)d_in[3];
    const float* b1     = (const float*)d_in[4];
    // d_in[5] Ws: dead (softmax over size-1 cluster axis == 1)
    const float* Wd     = (const float*)d_in[6];
    const float* bd     = (const float*)d_in[7];
    const float* Wc     = (const float*)d_in[8];
    const float* bc     = (const float*)d_in[9];
    float* out = (float*)d_out;

    // Idempotent, non-stream host calls (no allocation).
    cudaFuncSetAttribute(xw_kernel,
                         cudaFuncAttributeMaxDynamicSharedMemorySize, XW_SMEM);
    cudaFuncSetAttribute(main_kernel,
                         cudaFuncAttributeMaxDynamicSharedMemorySize, MAIN_SMEM);

    xw_kernel  <<<dim3(XMB, B_), 128, XW_SMEM  >>>(X, W1);
    main_kernel<<<dim3(MB2, B_), 256, MAIN_SMEM>>>(filtre, b1);
    head_kernel<<<B_, FC_>>>(Wd, bd, Wc, bc, out);
}